// round 3
// baseline (speedup 1.0000x reference)
#include <cuda_runtime.h>
#include <cstdint>
#include <cstddef>

// ============================================================================
// MultiRegionRNN on GB300 — fp32, one kernel launch per timestep (no device-
// side cross-CTA sync; the launch boundary is the barrier).
//
//  init_kernel : zero x-state and rate buffer 0
//  xp_kernel   : XP[t][b][jj] = X[t+1] @ [W_in_pmd; W_in_s1]^T + bias, all t
//  step_kernel : launched 499x. 129 CTAs, each owns a column slice of the
//                concatenated recurrent weight (staged SMEM from L2 each
//                step), computes its slice of R @ Wcat^T (block-sparse:
//                m1 K=1536, pmd K=1024, s1 K=512), leaky update + tanh,
//                writes rates to the other R buffer and x back to g_X.
//                Also computes the PREVIOUS step's readout (r_m1 @ W_out^T)
//                at kernel start (that data became consistent at the launch
//                boundary).
//  readout_final: readout for the last step.
// ============================================================================

#define NBLK 129
#define KT 128
#define RSP 132  // Rs row stride (floats), padded so bank = 4*b (conflict-free)

__device__ float g_XP[499u * 64u * 1024u];   // ~131 MB scratch (__device__ global)
__device__ float g_R[2u * 64u * 1536u];      // double-buffered rates, [buf][b][k]
__device__ float g_X[64u * 1536u];           // pre-activation state x, [b][k]

// ---------------------------------------------------------------------------
__global__ void init_kernel() {
    int idx = blockIdx.x * blockDim.x + threadIdx.x;
    if (idx < 64 * 1536) {
        g_X[idx] = 0.f;
        g_R[idx] = 0.f;   // buffer 0 (step 0 reads zeros = tanh(0) rates)
    }
}

// ---------------------------------------------------------------------------
// XP[t][b][jj], jj in [0,1024): jj<512 -> pmd input proj, else s1.
// grid (8 jblocks, 499 t), 256 threads. smem: Ws[128][101] + Xst[100][68].
// ---------------------------------------------------------------------------
__global__ void __launch_bounds__(256) xp_kernel(
    const float* __restrict__ X,
    const float* __restrict__ W_in_pmd,
    const float* __restrict__ W_in_s1,
    const float* __restrict__ b_pmd,
    const float* __restrict__ b_s1)
{
    extern __shared__ float sm[];
    float* Ws  = sm;               // [128][101]
    float* Xst = sm + 128 * 101;   // [100][68] transposed X tile

    const int t   = blockIdx.y;
    const int jb  = blockIdx.x;
    const int tid = threadIdx.x;

    for (int idx = tid; idx < 128 * 100; idx += 256) {
        int j = idx / 100, d = idx - j * 100;
        int jg = jb * 128 + j;
        float v = (jg < 512) ? W_in_pmd[jg * 100 + d] : W_in_s1[(jg - 512) * 100 + d];
        Ws[j * 101 + d] = v;
    }
    const float* Xt = X + (size_t)(t + 1) * 6400;
    for (int idx = tid; idx < 6400; idx += 256) {
        int b = idx / 100, d = idx - b * 100;
        Xst[d * 68 + b] = Xt[idx];
    }
    __syncthreads();

    const int j  = tid & 127;
    const int bh = tid >> 7;         // batch half (0/1)
    const int jg = jb * 128 + j;

    float acc[32];
#pragma unroll
    for (int i = 0; i < 32; i++) acc[i] = 0.f;

    for (int d = 0; d < 100; d++) {
        float w = Ws[j * 101 + d];
        const float4* xr = (const float4*)&Xst[d * 68 + bh * 32];
#pragma unroll
        for (int i = 0; i < 8; i++) {
            float4 xv = xr[i];
            acc[4 * i + 0] += w * xv.x;
            acc[4 * i + 1] += w * xv.y;
            acc[4 * i + 2] += w * xv.z;
            acc[4 * i + 3] += w * xv.w;
        }
    }
    float bias = (jg < 512) ? b_pmd[jg] : b_s1[jg - 512];
#pragma unroll
    for (int i = 0; i < 32; i++) {
        int b = bh * 32 + i;
        g_XP[(size_t)(t * 64 + b) * 1024 + jg] = acc[i] + bias;  // coalesced over warp
    }
}

// ---------------------------------------------------------------------------
struct RnnParams {
    const float* Wrec_m1;
    const float* Wrec_pmd;
    const float* Wrec_s1;
    const float* b_m1;
    const float* b_pmd;
    const float* b_s1;
    const float* Wpmd_m1;
    const float* Ws1_m1;
    const float* Wm1_pmd;
    const float* Wout;
    float* out;
};

template <int NC, int K, int REGION>
__device__ __forceinline__ void step_region(const RnnParams& P, int s, int colbase,
                                            int nc, float* sm, int cta)
{
    constexpr int JT    = NC / 4;
    constexpr int KP    = K + 4;
    constexpr int NT    = K / KT;
    constexpr int KBASE = (REGION == 2) ? 1024 : 0;

    float* Wsm = sm;
    float* Rs  = sm + NC * KP;

    const int tid = threadIdx.x;
    const int rb  = s & 1;         // rate buffer consumed this step
    const int wbuf = rb ^ 1;       // rate buffer produced this step

    // --- stage weight slice SMEM <- L2 (weights stay L2-resident: 7.3MB) ---
    for (int idx = tid; idx < NC * K; idx += 256) {
        int j = idx / K, k = idx - j * K;  // k local to this region's K window
        float v = 0.f;
        if (j < nc) {
            int jg = colbase + j;
            if (REGION == 0) {
                v = (k < 512)  ? P.Wrec_m1[jg * 512 + k]
                  : (k < 1024) ? P.Wpmd_m1[jg * 512 + (k - 512)]
                               : P.Ws1_m1[jg * 512 + (k - 1024)];
            } else if (REGION == 1) {
                int jp = jg - 512;
                v = (k < 512) ? P.Wm1_pmd[jp * 512 + k]
                              : P.Wrec_pmd[jp * 512 + (k - 512)];
            } else {
                v = P.Wrec_s1[(jg - 1024) * 512 + k];
            }
        }
        Wsm[j * KP + k] = v;
    }

    const int w  = tid >> 5;
    const int l  = tid & 31;
    const int bb = 8 * w + (l >> 2);  // batch row
    const int js = l & 3;             // column set

    // --- previous step's readout (data consistent at launch boundary) ---
    if (s > 0 && w < 5) {
        int p = cta * 5 + w;
        if (p < 640) {
            int b = p / 10, o = p - b * 10;
            const float* Rm = g_R + (size_t)rb * (64 * 1536) + b * 1536;
            const float* Wo = P.Wout + o * 512;
            float sum = 0.f;
            for (int k = l; k < 512; k += 32) sum += Rm[k] * Wo[k];
#pragma unroll
            for (int off = 16; off; off >>= 1)
                sum += __shfl_down_sync(0xffffffffu, sum, off);
            if (l == 0) P.out[(size_t)((s - 1) * 64 + b) * 10 + o] = sum;
        }
    }

    // --- block-sparse GEMM: acc[j] = sum_k R[bb][k] * W[j][k] ---
    const float* Rg = g_R + (size_t)rb * (64 * 1536);

    float acc[JT];
#pragma unroll
    for (int c = 0; c < JT; c++) acc[c] = 0.f;

    float4 pre[8];
#pragma unroll
    for (int i = 0; i < 8; i++) {
        int lin = tid + 256 * i;
        int b = lin >> 5, q = lin & 31;
        pre[i] = __ldcg((const float4*)(Rg + b * 1536 + KBASE + q * 4));
    }

    for (int kt = 0; kt < NT; kt++) {
        __syncthreads();   // Rs free (previous tile consumed / weights staged)
#pragma unroll
        for (int i = 0; i < 8; i++) {
            int lin = tid + 256 * i;
            int b = lin >> 5, q = lin & 31;
            *(float4*)&Rs[b * RSP + q * 4] = pre[i];
        }
        __syncthreads();   // Rs ready
        if (kt + 1 < NT) {
            int kwin = KBASE + (kt + 1) * KT;
#pragma unroll
            for (int i = 0; i < 8; i++) {
                int lin = tid + 256 * i;
                int b = lin >> 5, q = lin & 31;
                pre[i] = __ldcg((const float4*)(Rg + b * 1536 + kwin + q * 4));
            }
        }
        const float* Wrow = Wsm + kt * KT;
#pragma unroll 4
        for (int kk = 0; kk < KT; kk += 4) {
            float4 rv = *(const float4*)&Rs[bb * RSP + kk];
#pragma unroll
            for (int c = 0; c < JT; c++) {
                int j = js * JT + c;
                float4 wv = *(const float4*)&Wrow[j * KP + kk];
                acc[c] += rv.x * wv.x;
                acc[c] += rv.y * wv.y;
                acc[c] += rv.z * wv.z;
                acc[c] += rv.w * wv.w;
            }
        }
    }

    // --- epilogue: leaky update + tanh, publish rates + state ---
    const float A = 0.1f, OMA = 0.9f;
    float* Rw = g_R + (size_t)wbuf * (64 * 1536);
#pragma unroll
    for (int c = 0; c < JT; c++) {
        int j = js * JT + c;
        if (j < nc) {
            int jg = colbase + j;
            float bv = (REGION == 0) ? P.b_m1[jg]
                     : (REGION == 1) ? P.b_pmd[jg - 512]
                                     : P.b_s1[jg - 1024];
            float v = acc[c] + bv;
            if (REGION != 0) v += g_XP[(size_t)(s * 64 + bb) * 1024 + (jg - 512)];
            float x = OMA * g_X[bb * 1536 + jg] + A * v;
            g_X[bb * 1536 + jg] = x;
            Rw[bb * 1536 + jg] = tanhf(x);
        }
    }
}

__global__ void __launch_bounds__(256, 1) step_kernel(RnnParams P, int s) {
    extern __shared__ float sm[];
    const int cta = blockIdx.x;
    if (cta < 64) {
        step_region<8, 1536, 0>(P, s, cta * 8, 8, sm, cta);
    } else if (cta < 107) {
        int i = cta - 64;
        step_region<12, 1024, 1>(P, s, 512 + i * 12, (i < 42) ? 12 : 8, sm, cta);
    } else {
        int i = cta - 107;
        step_region<24, 512, 2>(P, s, 1024 + i * 24, (i < 21) ? 24 : 8, sm, cta);
    }
}

// --------------------------------------------------------------------------
// Final readout: out[498] from rate buffer 1 (written by step s=498).
// 80 CTAs x 8 warps = 640 (b,o) pairs.
// --------------------------------------------------------------------------
__global__ void __launch_bounds__(256) readout_final(const float* __restrict__ Wout,
                                                     float* __restrict__ out)
{
    const int w = threadIdx.x >> 5;
    const int l = threadIdx.x & 31;
    const int p = blockIdx.x * 8 + w;
    if (p >= 640) return;
    int b = p / 10, o = p - b * 10;
    const float* Rm = g_R + (size_t)1 * (64 * 1536) + b * 1536;
    const float* Wo = Wout + o * 512;
    float sum = 0.f;
    for (int k = l; k < 512; k += 32) sum += Rm[k] * Wo[k];
#pragma unroll
    for (int off = 16; off; off >>= 1)
        sum += __shfl_down_sync(0xffffffffu, sum, off);
    if (l == 0) out[(size_t)(498 * 64 + b) * 10 + o] = sum;
}

// ---------------------------------------------------------------------------
static const int XP_SMEM  = (128 * 101 + 100 * 68) * 4;   // 78912 B
static const int RNN_SMEM = (24 * 516 + 64 * RSP) * 4;    // 83328 B (max region)

extern "C" void kernel_launch(void* const* d_in, const int* in_sizes, int n_in,
                              void* d_out, int out_size)
{
    const float* X        = (const float*)d_in[0];
    const float* Wrec_m1  = (const float*)d_in[1];
    const float* Wrec_pmd = (const float*)d_in[2];
    const float* Wrec_s1  = (const float*)d_in[3];
    const float* b_m1     = (const float*)d_in[4];
    const float* b_pmd    = (const float*)d_in[5];
    const float* b_s1     = (const float*)d_in[6];
    const float* Wpmd_m1  = (const float*)d_in[7];
    const float* Ws1_m1   = (const float*)d_in[8];
    const float* Wm1_pmd  = (const float*)d_in[9];
    const float* W_in_pmd = (const float*)d_in[10];
    const float* W_in_s1  = (const float*)d_in[11];
    const float* Wout     = (const float*)d_in[12];
    float* out = (float*)d_out;

    static int attr_done = 0;
    if (!attr_done) {
        cudaFuncSetAttribute(xp_kernel,   cudaFuncAttributeMaxDynamicSharedMemorySize, XP_SMEM);
        cudaFuncSetAttribute(step_kernel, cudaFuncAttributeMaxDynamicSharedMemorySize, RNN_SMEM);
        attr_done = 1;
    }

    RnnParams P;
    P.Wrec_m1 = Wrec_m1; P.Wrec_pmd = Wrec_pmd; P.Wrec_s1 = Wrec_s1;
    P.b_m1 = b_m1; P.b_pmd = b_pmd; P.b_s1 = b_s1;
    P.Wpmd_m1 = Wpmd_m1; P.Ws1_m1 = Ws1_m1; P.Wm1_pmd = Wm1_pmd;
    P.Wout = Wout; P.out = out;

    init_kernel<<<(64 * 1536 + 255) / 256, 256>>>();
    xp_kernel<<<dim3(8, 499), 256, XP_SMEM>>>(X, W_in_pmd, W_in_s1, b_pmd, b_s1);
    for (int s = 0; s < 499; s++)
        step_kernel<<<NBLK, 256, RNN_SMEM>>>(P, s);
    readout_final<<<80, 256>>>(Wout, out);
}

// round 5
// speedup vs baseline: 1.3702x; 1.3702x over previous
#include <cuda_runtime.h>
#include <cstdint>
#include <cstddef>

// ============================================================================
// MultiRegionRNN on GB300 — fp32, one kernel launch per timestep.
// Round 4: fix round-3 staging bug (tiles were only 1/4 staged -> NaN).
//   - 2D register tiling TM=8 x TN=nc/4, split-K across 8 warps (16-k windows)
//   - conflict-free smem layouts (row stride 132, strided thread tiles)
//   - cp.async double-buffered R+W tile staging (FULL 32 quads per row now)
//   - cross-warp k-partial reduction via bank-padded smem (stride 72)
// ============================================================================

#define NBLK 129
#define KT 128
#define RSP 132                 // R tile row stride (floats)
#define WSP 132                 // W tile row stride (floats)
#define RJ  72                  // reduction row stride (floats)

__device__ float g_XP[499u * 64u * 1024u];   // hoisted input projections
__device__ float g_R[2u * 64u * 1536u];      // double-buffered rates [buf][b][k]
__device__ float g_X[1536u * 64u];           // pre-activation state [j][b]

// ---------------------------------------------------------------------------
__global__ void init_kernel() {
    int idx = blockIdx.x * blockDim.x + threadIdx.x;
    if (idx < 64 * 1536) {
        g_X[idx] = 0.f;
        g_R[idx] = 0.f;   // buffer 0: step 0 reads zeros = tanh(0) rates
    }
}

// ---------------------------------------------------------------------------
// XP[t][b][jj], jj in [0,1024): jj<512 -> pmd input proj, else s1.
// ---------------------------------------------------------------------------
__global__ void __launch_bounds__(256) xp_kernel(
    const float* __restrict__ X,
    const float* __restrict__ W_in_pmd,
    const float* __restrict__ W_in_s1,
    const float* __restrict__ b_pmd,
    const float* __restrict__ b_s1)
{
    extern __shared__ float sm[];
    float* Ws  = sm;               // [128][101]
    float* Xst = sm + 128 * 101;   // [100][68]

    const int t   = blockIdx.y;
    const int jb  = blockIdx.x;
    const int tid = threadIdx.x;

    for (int idx = tid; idx < 128 * 100; idx += 256) {
        int j = idx / 100, d = idx - j * 100;
        int jg = jb * 128 + j;
        float v = (jg < 512) ? W_in_pmd[jg * 100 + d] : W_in_s1[(jg - 512) * 100 + d];
        Ws[j * 101 + d] = v;
    }
    const float* Xt = X + (size_t)(t + 1) * 6400;
    for (int idx = tid; idx < 6400; idx += 256) {
        int b = idx / 100, d = idx - b * 100;
        Xst[d * 68 + b] = Xt[idx];
    }
    __syncthreads();

    const int j  = tid & 127;
    const int bh = tid >> 7;
    const int jg = jb * 128 + j;

    float acc[32];
#pragma unroll
    for (int i = 0; i < 32; i++) acc[i] = 0.f;

    for (int d = 0; d < 100; d++) {
        float w = Ws[j * 101 + d];
        const float4* xr = (const float4*)&Xst[d * 68 + bh * 32];
#pragma unroll
        for (int i = 0; i < 8; i++) {
            float4 xv = xr[i];
            acc[4 * i + 0] += w * xv.x;
            acc[4 * i + 1] += w * xv.y;
            acc[4 * i + 2] += w * xv.z;
            acc[4 * i + 3] += w * xv.w;
        }
    }
    float bias = (jg < 512) ? b_pmd[jg] : b_s1[jg - 512];
#pragma unroll
    for (int i = 0; i < 32; i++) {
        int b = bh * 32 + i;
        g_XP[(size_t)(t * 64 + b) * 1024 + jg] = acc[i] + bias;
    }
}

// ---------------------------------------------------------------------------
struct RnnParams {
    const float* Wrec_m1;
    const float* Wrec_pmd;
    const float* Wrec_s1;
    const float* b_m1;
    const float* b_pmd;
    const float* b_s1;
    const float* Wpmd_m1;
    const float* Ws1_m1;
    const float* Wm1_pmd;
    const float* Wout;
    float* out;
};

__device__ __forceinline__ void cp16(unsigned dst, const void* src) {
    asm volatile("cp.async.cg.shared.global [%0], [%1], 16;\n" :: "r"(dst), "l"(src));
}
__device__ __forceinline__ void cp_commit() {
    asm volatile("cp.async.commit_group;\n");
}
template <int N>
__device__ __forceinline__ void cp_wait() {
    asm volatile("cp.async.wait_group %0;\n" :: "n"(N));
}
__device__ __forceinline__ unsigned smaddr(const void* p) {
    return (unsigned)__cvta_generic_to_shared(p);
}

// Source row pointer for weight tile; k0 = kt*128 (region-local column)
template <int REGION>
__device__ __forceinline__ const float* wrow(const RnnParams& P, int jg, int k0) {
    if (REGION == 0) {
        if (k0 < 512)  return P.Wrec_m1 + jg * 512 + k0;
        if (k0 < 1024) return P.Wpmd_m1 + jg * 512 + (k0 - 512);
        return P.Ws1_m1 + jg * 512 + (k0 - 1024);
    } else if (REGION == 1) {
        int jp = jg - 512;
        if (k0 < 512) return P.Wm1_pmd + jp * 512 + k0;
        return P.Wrec_pmd + jp * 512 + (k0 - 512);
    } else {
        return P.Wrec_s1 + (jg - 1024) * 512 + k0;
    }
}

template <int NC, int K, int REGION, int TN>
__device__ __forceinline__ void step_region(const RnnParams& P, int s, int colbase,
                                            int nc, float* sm, int cta)
{
    constexpr int NT    = K / KT;
    constexpr int KBASE = (REGION == 2) ? 1024 : 0;

    float* Rs[2]; float* Wsb[2];
    Rs[0]  = sm;
    Rs[1]  = sm + 64 * RSP;
    Wsb[0] = sm + 2 * 64 * RSP;
    Wsb[1] = Wsb[0] + NC * WSP;
    float* red = sm;   // overlay (used after mainloop; tiles consumed by then)

    const int tid  = threadIdx.x;
    const int w    = tid >> 5;      // warp = k-window index
    const int lane = tid & 31;
    const int rg   = lane & 7;      // rows rg + 8i
    const int cg   = lane >> 3;     // cols cg + 4t

    const int rb   = s & 1;
    const int wbuf = rb ^ 1;
    const float* Rg = g_R + (size_t)rb * (64 * 1536) + KBASE;

    // ---- stage tile 0 (FULL: 32 quads per 128-float row) ----
    {
        for (int c = tid; c < 64 * 32; c += 256) {
            int b = c >> 5, q = c & 31;
            cp16(smaddr(Rs[0] + b * RSP + q * 4), Rg + b * 1536 + q * 4);
        }
        for (int c = tid; c < NC * 32; c += 256) {
            int j = c >> 5, q = c & 31;
            int jj = (j < nc) ? j : 0;
            cp16(smaddr(Wsb[0] + j * WSP + q * 4),
                 wrow<REGION>(P, colbase + jj, 0) + q * 4);
        }
        cp_commit();
    }

    // ---- previous step's readout (data consistent at launch boundary) ----
    if (s > 0 && w < 5) {
        int p = cta * 5 + w;
        if (p < 640) {
            int b = p / 10, o = p - b * 10;
            const float* Rm = g_R + (size_t)rb * (64 * 1536) + b * 1536;
            const float* Wo = P.Wout + o * 512;
            float sum = 0.f;
            for (int k = lane; k < 512; k += 32) sum += Rm[k] * Wo[k];
#pragma unroll
            for (int off = 16; off; off >>= 1)
                sum += __shfl_down_sync(0xffffffffu, sum, off);
            if (lane == 0) P.out[(size_t)((s - 1) * 64 + b) * 10 + o] = sum;
        }
    }

    // ---- mainloop: double-buffered tiles, warp k-window = [w*16, (w+1)*16) ----
    float acc[8 * TN];
#pragma unroll
    for (int i = 0; i < 8 * TN; i++) acc[i] = 0.f;

    for (int kt = 0; kt < NT; kt++) {
        const int buf = kt & 1;
        if (kt + 1 < NT) {
            const int nb = buf ^ 1;
            const int kg = (kt + 1) * KT;
            for (int c = tid; c < 64 * 32; c += 256) {
                int b = c >> 5, q = c & 31;
                cp16(smaddr(Rs[nb] + b * RSP + q * 4), Rg + b * 1536 + kg + q * 4);
            }
            for (int c = tid; c < NC * 32; c += 256) {
                int j = c >> 5, q = c & 31;
                int jj = (j < nc) ? j : 0;
                cp16(smaddr(Wsb[nb] + j * WSP + q * 4),
                     wrow<REGION>(P, colbase + jj, kg) + q * 4);
            }
            cp_commit();
            cp_wait<1>();   // tile kt's group done
        } else {
            cp_wait<0>();
        }
        __syncthreads();   // tile kt visible to all warps

        const float* Rt = Rs[buf];
        const float* Wt = Wsb[buf];
        const int kw = w << 4;
#pragma unroll
        for (int q = 0; q < 4; q++) {
            const int ko = kw + (q << 2);
            float4 rv[8];
#pragma unroll
            for (int i = 0; i < 8; i++)
                rv[i] = *(const float4*)&Rt[(rg + 8 * i) * RSP + ko];
            float4 wv[TN];
#pragma unroll
            for (int t = 0; t < TN; t++)
                wv[t] = *(const float4*)&Wt[(cg + 4 * t) * WSP + ko];
#pragma unroll
            for (int i = 0; i < 8; i++) {
#pragma unroll
                for (int t = 0; t < TN; t++) {
                    acc[i * TN + t] += rv[i].x * wv[t].x;
                    acc[i * TN + t] += rv[i].y * wv[t].y;
                    acc[i * TN + t] += rv[i].z * wv[t].z;
                    acc[i * TN + t] += rv[i].w * wv[t].w;
                }
            }
        }
        __syncthreads();   // buffer free for restage next iter
    }

    // ---- cross-warp k-partial reduction (overlay smem) ----
#pragma unroll
    for (int t = 0; t < TN; t++) {
        int j = cg + 4 * t;
#pragma unroll
        for (int i = 0; i < 8; i++) {
            int b = rg + 8 * i;
            red[(w * NC + j) * RJ + b] = acc[i * TN + t];
        }
    }
    __syncthreads();

    // ---- epilogue: reduce 8 partials, leaky update + tanh, publish ----
    const float A = 0.1f, OMA = 0.9f;
    const float* bias = (REGION == 0) ? P.b_m1 + colbase
                      : (REGION == 1) ? P.b_pmd + (colbase - 512)
                                      : P.b_s1 + (colbase - 1024);
    float* Rw = g_R + (size_t)wbuf * (64 * 1536);
    const int nout = 64 * nc;
    for (int o = tid; o < nout; o += 256) {
        int j = o >> 6, b = o & 63;
        float sum = 0.f;
#pragma unroll
        for (int ww = 0; ww < 8; ww++) sum += red[(ww * NC + j) * RJ + b];
        int jg = colbase + j;
        float v = sum + bias[j];
        if (REGION != 0) v += g_XP[(size_t)(s * 64 + b) * 1024 + (jg - 512)];
        float x = OMA * g_X[jg * 64 + b] + A * v;
        g_X[jg * 64 + b] = x;
        Rw[b * 1536 + jg] = tanhf(x);
    }
}

__global__ void __launch_bounds__(256, 1) step_kernel(RnnParams P, int s) {
    extern __shared__ float sm[];
    const int cta = blockIdx.x;
    if (cta < 64) {
        step_region<8, 1536, 0, 2>(P, s, cta * 8, 8, sm, cta);
    } else if (cta < 107) {
        int i = cta - 64;
        step_region<12, 1024, 1, 3>(P, s, 512 + i * 12, (i < 42) ? 12 : 8, sm, cta);
    } else {
        int i = cta - 107;
        step_region<24, 512, 2, 6>(P, s, 1024 + i * 24, (i < 21) ? 24 : 8, sm, cta);
    }
}

// --------------------------------------------------------------------------
// Final readout: out[498] from rate buffer 1 (written by step s=498).
// --------------------------------------------------------------------------
__global__ void __launch_bounds__(256) readout_final(const float* __restrict__ Wout,
                                                     float* __restrict__ out)
{
    const int w = threadIdx.x >> 5;
    const int l = threadIdx.x & 31;
    const int p = blockIdx.x * 8 + w;
    if (p >= 640) return;
    int b = p / 10, o = p - b * 10;
    const float* Rm = g_R + (size_t)1 * (64 * 1536) + b * 1536;
    const float* Wo = Wout + o * 512;
    float sum = 0.f;
    for (int k = l; k < 512; k += 32) sum += Rm[k] * Wo[k];
#pragma unroll
    for (int off = 16; off; off >>= 1)
        sum += __shfl_down_sync(0xffffffffu, sum, off);
    if (l == 0) out[(size_t)(498 * 64 + b) * 10 + o] = sum;
}

// ---------------------------------------------------------------------------
static const int XP_SMEM  = (128 * 101 + 100 * 68) * 4;              // 78912 B
static const int RNN_SMEM = (2 * 64 * RSP + 2 * 24 * WSP) * 4;       // 92928 B

extern "C" void kernel_launch(void* const* d_in, const int* in_sizes, int n_in,
                              void* d_out, int out_size)
{
    const float* X        = (const float*)d_in[0];
    const float* Wrec_m1  = (const float*)d_in[1];
    const float* Wrec_pmd = (const float*)d_in[2];
    const float* Wrec_s1  = (const float*)d_in[3];
    const float* b_m1     = (const float*)d_in[4];
    const float* b_pmd    = (const float*)d_in[5];
    const float* b_s1     = (const float*)d_in[6];
    const float* Wpmd_m1  = (const float*)d_in[7];
    const float* Ws1_m1   = (const float*)d_in[8];
    const float* Wm1_pmd  = (const float*)d_in[9];
    const float* W_in_pmd = (const float*)d_in[10];
    const float* W_in_s1  = (const float*)d_in[11];
    const float* Wout     = (const float*)d_in[12];
    float* out = (float*)d_out;

    cudaFuncSetAttribute(xp_kernel,   cudaFuncAttributeMaxDynamicSharedMemorySize, XP_SMEM);
    cudaFuncSetAttribute(step_kernel, cudaFuncAttributeMaxDynamicSharedMemorySize, RNN_SMEM);

    RnnParams P;
    P.Wrec_m1 = Wrec_m1; P.Wrec_pmd = Wrec_pmd; P.Wrec_s1 = Wrec_s1;
    P.b_m1 = b_m1; P.b_pmd = b_pmd; P.b_s1 = b_s1;
    P.Wpmd_m1 = Wpmd_m1; P.Ws1_m1 = Ws1_m1; P.Wm1_pmd = Wm1_pmd;
    P.Wout = Wout; P.out = out;

    init_kernel<<<(64 * 1536 + 255) / 256, 256>>>();
    xp_kernel<<<dim3(8, 499), 256, XP_SMEM>>>(X, W_in_pmd, W_in_s1, b_pmd, b_s1);
    for (int s = 0; s < 499; s++)
        step_kernel<<<NBLK, 256, RNN_SMEM>>>(P, s);
    readout_final<<<80, 256>>>(Wout, out);
}

// round 6
// speedup vs baseline: 1.5811x; 1.1539x over previous
#include <cuda_runtime.h>
#include <cstdint>
#include <cstddef>

// ============================================================================
// MultiRegionRNN on GB300 — fp32, one kernel launch per timestep.
// Round 5: occupancy + register-pressure fix.
//   - 512 threads/CTA (16 warps, split-K windows of 8)
//   - region rebalance: TN capped at 4 (s1: 32 CTAs x 16 cols), grid = 139
//   - same cp.async double-buffered tiles, bank-clean layouts
// ============================================================================

#define NBLK 139
#define KT 128
#define RSP 132                 // R tile row stride (floats)
#define WSP 132                 // W tile row stride (floats)
#define RJ  72                  // reduction row stride (floats)

__device__ float g_XP[499u * 64u * 1024u];   // hoisted input projections
__device__ float g_R[2u * 64u * 1536u];      // double-buffered rates [buf][b][k]
__device__ float g_X[1536u * 64u];           // pre-activation state [j][b]

// ---------------------------------------------------------------------------
__global__ void init_kernel() {
    int idx = blockIdx.x * blockDim.x + threadIdx.x;
    if (idx < 64 * 1536) {
        g_X[idx] = 0.f;
        g_R[idx] = 0.f;   // buffer 0: step 0 reads zeros = tanh(0) rates
    }
}

// ---------------------------------------------------------------------------
// XP[t][b][jj], jj in [0,1024): jj<512 -> pmd input proj, else s1.
// ---------------------------------------------------------------------------
__global__ void __launch_bounds__(256) xp_kernel(
    const float* __restrict__ X,
    const float* __restrict__ W_in_pmd,
    const float* __restrict__ W_in_s1,
    const float* __restrict__ b_pmd,
    const float* __restrict__ b_s1)
{
    extern __shared__ float sm[];
    float* Ws  = sm;               // [128][101]
    float* Xst = sm + 128 * 101;   // [100][68]

    const int t   = blockIdx.y;
    const int jb  = blockIdx.x;
    const int tid = threadIdx.x;

    for (int idx = tid; idx < 128 * 100; idx += 256) {
        int j = idx / 100, d = idx - j * 100;
        int jg = jb * 128 + j;
        float v = (jg < 512) ? W_in_pmd[jg * 100 + d] : W_in_s1[(jg - 512) * 100 + d];
        Ws[j * 101 + d] = v;
    }
    const float* Xt = X + (size_t)(t + 1) * 6400;
    for (int idx = tid; idx < 6400; idx += 256) {
        int b = idx / 100, d = idx - b * 100;
        Xst[d * 68 + b] = Xt[idx];
    }
    __syncthreads();

    const int j  = tid & 127;
    const int bh = tid >> 7;
    const int jg = jb * 128 + j;

    float acc[32];
#pragma unroll
    for (int i = 0; i < 32; i++) acc[i] = 0.f;

    for (int d = 0; d < 100; d++) {
        float w = Ws[j * 101 + d];
        const float4* xr = (const float4*)&Xst[d * 68 + bh * 32];
#pragma unroll
        for (int i = 0; i < 8; i++) {
            float4 xv = xr[i];
            acc[4 * i + 0] += w * xv.x;
            acc[4 * i + 1] += w * xv.y;
            acc[4 * i + 2] += w * xv.z;
            acc[4 * i + 3] += w * xv.w;
        }
    }
    float bias = (jg < 512) ? b_pmd[jg] : b_s1[jg - 512];
#pragma unroll
    for (int i = 0; i < 32; i++) {
        int b = bh * 32 + i;
        g_XP[(size_t)(t * 64 + b) * 1024 + jg] = acc[i] + bias;
    }
}

// ---------------------------------------------------------------------------
struct RnnParams {
    const float* Wrec_m1;
    const float* Wrec_pmd;
    const float* Wrec_s1;
    const float* b_m1;
    const float* b_pmd;
    const float* b_s1;
    const float* Wpmd_m1;
    const float* Ws1_m1;
    const float* Wm1_pmd;
    const float* Wout;
    float* out;
};

__device__ __forceinline__ void cp16(unsigned dst, const void* src) {
    asm volatile("cp.async.cg.shared.global [%0], [%1], 16;\n" :: "r"(dst), "l"(src));
}
__device__ __forceinline__ void cp_commit() {
    asm volatile("cp.async.commit_group;\n");
}
template <int N>
__device__ __forceinline__ void cp_wait() {
    asm volatile("cp.async.wait_group %0;\n" :: "n"(N));
}
__device__ __forceinline__ unsigned smaddr(const void* p) {
    return (unsigned)__cvta_generic_to_shared(p);
}

// Source row pointer for weight tile; k0 = kt*128 (region-local column)
template <int REGION>
__device__ __forceinline__ const float* wrow(const RnnParams& P, int jg, int k0) {
    if (REGION == 0) {
        if (k0 < 512)  return P.Wrec_m1 + jg * 512 + k0;
        if (k0 < 1024) return P.Wpmd_m1 + jg * 512 + (k0 - 512);
        return P.Ws1_m1 + jg * 512 + (k0 - 1024);
    } else if (REGION == 1) {
        int jp = jg - 512;
        if (k0 < 512) return P.Wm1_pmd + jp * 512 + k0;
        return P.Wrec_pmd + jp * 512 + (k0 - 512);
    } else {
        return P.Wrec_s1 + (jg - 1024) * 512 + k0;
    }
}

template <int NC, int K, int REGION, int TN>
__device__ __forceinline__ void step_region(const RnnParams& P, int s, int colbase,
                                            int nc, float* sm, int cta)
{
    constexpr int NT    = K / KT;
    constexpr int KBASE = (REGION == 2) ? 1024 : 0;

    float* Rs[2]; float* Wsb[2];
    Rs[0]  = sm;
    Rs[1]  = sm + 64 * RSP;
    Wsb[0] = sm + 2 * 64 * RSP;
    Wsb[1] = Wsb[0] + NC * WSP;
    float* red = sm;   // overlay (used after mainloop; tiles consumed by then)

    const int tid  = threadIdx.x;
    const int w    = tid >> 5;      // warp = k-window index (16 windows of 8)
    const int lane = tid & 31;
    const int rg   = lane & 7;      // rows rg + 8i
    const int cg   = lane >> 3;     // cols cg + 4t

    const int rb   = s & 1;
    const int wbuf = rb ^ 1;
    const float* Rg = g_R + (size_t)rb * (64 * 1536) + KBASE;

    // ---- stage tile 0 (32 quads per 128-float row) ----
    {
        for (int c = tid; c < 64 * 32; c += 512) {
            int b = c >> 5, q = c & 31;
            cp16(smaddr(Rs[0] + b * RSP + q * 4), Rg + b * 1536 + q * 4);
        }
        for (int c = tid; c < NC * 32; c += 512) {
            int j = c >> 5, q = c & 31;
            int jj = (j < nc) ? j : 0;
            cp16(smaddr(Wsb[0] + j * WSP + q * 4),
                 wrow<REGION>(P, colbase + jj, 0) + q * 4);
        }
        cp_commit();
    }

    // ---- previous step's readout (data consistent at launch boundary) ----
    if (s > 0 && w < 5) {
        int p = cta * 5 + w;
        if (p < 640) {
            int b = p / 10, o = p - b * 10;
            const float* Rm = g_R + (size_t)rb * (64 * 1536) + b * 1536;
            const float* Wo = P.Wout + o * 512;
            float sum = 0.f;
            for (int k = lane; k < 512; k += 32) sum += Rm[k] * Wo[k];
#pragma unroll
            for (int off = 16; off; off >>= 1)
                sum += __shfl_down_sync(0xffffffffu, sum, off);
            if (lane == 0) P.out[(size_t)((s - 1) * 64 + b) * 10 + o] = sum;
        }
    }

    // ---- mainloop: double-buffered tiles, warp k-window = [w*8, (w+1)*8) ----
    float acc[8 * TN];
#pragma unroll
    for (int i = 0; i < 8 * TN; i++) acc[i] = 0.f;

    for (int kt = 0; kt < NT; kt++) {
        const int buf = kt & 1;
        if (kt + 1 < NT) {
            const int nb = buf ^ 1;
            const int kg = (kt + 1) * KT;
            for (int c = tid; c < 64 * 32; c += 512) {
                int b = c >> 5, q = c & 31;
                cp16(smaddr(Rs[nb] + b * RSP + q * 4), Rg + b * 1536 + kg + q * 4);
            }
            for (int c = tid; c < NC * 32; c += 512) {
                int j = c >> 5, q = c & 31;
                int jj = (j < nc) ? j : 0;
                cp16(smaddr(Wsb[nb] + j * WSP + q * 4),
                     wrow<REGION>(P, colbase + jj, kg) + q * 4);
            }
            cp_commit();
            cp_wait<1>();   // tile kt's group done
        } else {
            cp_wait<0>();
        }
        __syncthreads();   // tile kt visible to all warps

        const float* Rt = Rs[buf];
        const float* Wt = Wsb[buf];
        const int kw = w << 3;
#pragma unroll
        for (int q = 0; q < 2; q++) {
            const int ko = kw + (q << 2);
            float4 rv[8];
#pragma unroll
            for (int i = 0; i < 8; i++)
                rv[i] = *(const float4*)&Rt[(rg + 8 * i) * RSP + ko];
            float4 wv[TN];
#pragma unroll
            for (int t = 0; t < TN; t++)
                wv[t] = *(const float4*)&Wt[(cg + 4 * t) * WSP + ko];
#pragma unroll
            for (int i = 0; i < 8; i++) {
#pragma unroll
                for (int t = 0; t < TN; t++) {
                    acc[i * TN + t] += rv[i].x * wv[t].x;
                    acc[i * TN + t] += rv[i].y * wv[t].y;
                    acc[i * TN + t] += rv[i].z * wv[t].z;
                    acc[i * TN + t] += rv[i].w * wv[t].w;
                }
            }
        }
        __syncthreads();   // buffer free for restage next iter
    }

    // ---- cross-warp k-partial reduction (overlay smem) ----
#pragma unroll
    for (int t = 0; t < TN; t++) {
        int j = cg + 4 * t;
#pragma unroll
        for (int i = 0; i < 8; i++) {
            int b = rg + 8 * i;
            red[(w * NC + j) * RJ + b] = acc[i * TN + t];
        }
    }
    __syncthreads();

    // ---- epilogue: reduce 16 partials, leaky update + tanh, publish ----
    const float A = 0.1f, OMA = 0.9f;
    const float* bias = (REGION == 0) ? P.b_m1 + colbase
                      : (REGION == 1) ? P.b_pmd + (colbase - 512)
                                      : P.b_s1 + (colbase - 1024);
    float* Rw = g_R + (size_t)wbuf * (64 * 1536);
    const int nout = 64 * nc;
    for (int o = tid; o < nout; o += 512) {
        int j = o >> 6, b = o & 63;
        float sum = 0.f;
#pragma unroll
        for (int ww = 0; ww < 16; ww++) sum += red[(ww * NC + j) * RJ + b];
        int jg = colbase + j;
        float v = sum + bias[j];
        if (REGION != 0) v += g_XP[(size_t)(s * 64 + b) * 1024 + (jg - 512)];
        float x = OMA * g_X[jg * 64 + b] + A * v;
        g_X[jg * 64 + b] = x;
        Rw[b * 1536 + jg] = tanhf(x);
    }
}

__global__ void __launch_bounds__(512, 1) step_kernel(RnnParams P, int s) {
    extern __shared__ float sm[];
    const int cta = blockIdx.x;
    if (cta < 64) {
        step_region<8, 1536, 0, 2>(P, s, cta * 8, 8, sm, cta);
    } else if (cta < 107) {
        int i = cta - 64;
        step_region<12, 1024, 1, 3>(P, s, 512 + i * 12, (i < 42) ? 12 : 8, sm, cta);
    } else {
        int i = cta - 107;
        step_region<16, 512, 2, 4>(P, s, 1024 + i * 16, 16, sm, cta);
    }
}

// --------------------------------------------------------------------------
// Final readout: out[498] from rate buffer 1 (written by step s=498).
// --------------------------------------------------------------------------
__global__ void __launch_bounds__(256) readout_final(const float* __restrict__ Wout,
                                                     float* __restrict__ out)
{
    const int w = threadIdx.x >> 5;
    const int l = threadIdx.x & 31;
    const int p = blockIdx.x * 8 + w;
    if (p >= 640) return;
    int b = p / 10, o = p - b * 10;
    const float* Rm = g_R + (size_t)1 * (64 * 1536) + b * 1536;
    const float* Wo = Wout + o * 512;
    float sum = 0.f;
    for (int k = l; k < 512; k += 32) sum += Rm[k] * Wo[k];
#pragma unroll
    for (int off = 16; off; off >>= 1)
        sum += __shfl_down_sync(0xffffffffu, sum, off);
    if (l == 0) out[(size_t)(498 * 64 + b) * 10 + o] = sum;
}

// ---------------------------------------------------------------------------
static const int XP_SMEM  = (128 * 101 + 100 * 68) * 4;              // 78912 B
static const int RNN_SMEM = (2 * 64 * RSP + 2 * 16 * WSP) * 4;       // 84480 B

extern "C" void kernel_launch(void* const* d_in, const int* in_sizes, int n_in,
                              void* d_out, int out_size)
{
    const float* X        = (const float*)d_in[0];
    const float* Wrec_m1  = (const float*)d_in[1];
    const float* Wrec_pmd = (const float*)d_in[2];
    const float* Wrec_s1  = (const float*)d_in[3];
    const float* b_m1     = (const float*)d_in[4];
    const float* b_pmd    = (const float*)d_in[5];
    const float* b_s1     = (const float*)d_in[6];
    const float* Wpmd_m1  = (const float*)d_in[7];
    const float* Ws1_m1   = (const float*)d_in[8];
    const float* Wm1_pmd  = (const float*)d_in[9];
    const float* W_in_pmd = (const float*)d_in[10];
    const float* W_in_s1  = (const float*)d_in[11];
    const float* Wout     = (const float*)d_in[12];
    float* out = (float*)d_out;

    cudaFuncSetAttribute(xp_kernel,   cudaFuncAttributeMaxDynamicSharedMemorySize, XP_SMEM);
    cudaFuncSetAttribute(step_kernel, cudaFuncAttributeMaxDynamicSharedMemorySize, RNN_SMEM);

    RnnParams P;
    P.Wrec_m1 = Wrec_m1; P.Wrec_pmd = Wrec_pmd; P.Wrec_s1 = Wrec_s1;
    P.b_m1 = b_m1; P.b_pmd = b_pmd; P.b_s1 = b_s1;
    P.Wpmd_m1 = Wpmd_m1; P.Ws1_m1 = Ws1_m1; P.Wm1_pmd = Wm1_pmd;
    P.Wout = Wout; P.out = out;

    init_kernel<<<(64 * 1536 + 255) / 256, 256>>>();
    xp_kernel<<<dim3(8, 499), 256, XP_SMEM>>>(X, W_in_pmd, W_in_s1, b_pmd, b_s1);
    for (int s = 0; s < 499; s++)
        step_kernel<<<NBLK, 512, RNN_SMEM>>>(P, s);
    readout_final<<<80, 256>>>(Wout, out);
}

// round 7
// speedup vs baseline: 1.5843x; 1.0021x over previous
#include <cuda_runtime.h>
#include <cstdint>
#include <cstddef>

// ============================================================================
// MultiRegionRNN on GB300 — fp32, one kernel launch per timestep.
// Round 6: FFMA2 (fma.rn.f32x2 packed along k) + 1024 threads/CTA.
//   - packed math: acc2.lo accumulates even k, .hi odd k; add halves at end.
//     R/W tiles are k-contiguous -> float4 = 2 packed operands, no repacking.
//   - 32 warps: m1 = 16 k-windows x 2 row-halves; pmd/s1 = 8 k-windows x
//     4 row-quarters. All paths fit the 64-reg cap of launch_bounds(1024).
//   - cp.async double-buffered tiles; bank-exact smem layouts.
// ============================================================================

#define NBLK 139
#define KT 128
#define RSP 132                 // R tile row stride (floats)
#define WSP 132                 // W tile row stride (floats)
#define RJ  72                  // reduction row stride (floats)

typedef unsigned long long u64t;

__device__ float g_XP[499u * 64u * 1024u];   // hoisted input projections
__device__ float g_R[2u * 64u * 1536u];      // double-buffered rates [buf][b][k]
__device__ float g_X[1536u * 64u];           // pre-activation state [j][b]

#define FMA_F32X2(d, a, b) \
    asm("fma.rn.f32x2 %0, %1, %2, %0;" : "+l"(d) : "l"(a), "l"(b))

// ---------------------------------------------------------------------------
__global__ void init_kernel() {
    int idx = blockIdx.x * blockDim.x + threadIdx.x;
    if (idx < 64 * 1536) {
        g_X[idx] = 0.f;
        g_R[idx] = 0.f;   // buffer 0: step 0 reads zeros = tanh(0) rates
    }
}

// ---------------------------------------------------------------------------
// XP[t][b][jj], jj in [0,1024): jj<512 -> pmd input proj, else s1.
// ---------------------------------------------------------------------------
__global__ void __launch_bounds__(256) xp_kernel(
    const float* __restrict__ X,
    const float* __restrict__ W_in_pmd,
    const float* __restrict__ W_in_s1,
    const float* __restrict__ b_pmd,
    const float* __restrict__ b_s1)
{
    extern __shared__ float sm[];
    float* Ws  = sm;               // [128][101]
    float* Xst = sm + 128 * 101;   // [100][68]

    const int t   = blockIdx.y;
    const int jb  = blockIdx.x;
    const int tid = threadIdx.x;

    for (int idx = tid; idx < 128 * 100; idx += 256) {
        int j = idx / 100, d = idx - j * 100;
        int jg = jb * 128 + j;
        float v = (jg < 512) ? W_in_pmd[jg * 100 + d] : W_in_s1[(jg - 512) * 100 + d];
        Ws[j * 101 + d] = v;
    }
    const float* Xt = X + (size_t)(t + 1) * 6400;
    for (int idx = tid; idx < 6400; idx += 256) {
        int b = idx / 100, d = idx - b * 100;
        Xst[d * 68 + b] = Xt[idx];
    }
    __syncthreads();

    const int j  = tid & 127;
    const int bh = tid >> 7;
    const int jg = jb * 128 + j;

    float acc[32];
#pragma unroll
    for (int i = 0; i < 32; i++) acc[i] = 0.f;

    for (int d = 0; d < 100; d++) {
        float w = Ws[j * 101 + d];
        const float4* xr = (const float4*)&Xst[d * 68 + bh * 32];
#pragma unroll
        for (int i = 0; i < 8; i++) {
            float4 xv = xr[i];
            acc[4 * i + 0] += w * xv.x;
            acc[4 * i + 1] += w * xv.y;
            acc[4 * i + 2] += w * xv.z;
            acc[4 * i + 3] += w * xv.w;
        }
    }
    float bias = (jg < 512) ? b_pmd[jg] : b_s1[jg - 512];
#pragma unroll
    for (int i = 0; i < 32; i++) {
        int b = bh * 32 + i;
        g_XP[(size_t)(t * 64 + b) * 1024 + jg] = acc[i] + bias;
    }
}

// ---------------------------------------------------------------------------
struct RnnParams {
    const float* Wrec_m1;
    const float* Wrec_pmd;
    const float* Wrec_s1;
    const float* b_m1;
    const float* b_pmd;
    const float* b_s1;
    const float* Wpmd_m1;
    const float* Ws1_m1;
    const float* Wm1_pmd;
    const float* Wout;
    float* out;
};

__device__ __forceinline__ void cp16(unsigned dst, const void* src) {
    asm volatile("cp.async.cg.shared.global [%0], [%1], 16;\n" :: "r"(dst), "l"(src));
}
__device__ __forceinline__ void cp_commit() {
    asm volatile("cp.async.commit_group;\n");
}
template <int N>
__device__ __forceinline__ void cp_wait() {
    asm volatile("cp.async.wait_group %0;\n" :: "n"(N));
}
__device__ __forceinline__ unsigned smaddr(const void* p) {
    return (unsigned)__cvta_generic_to_shared(p);
}

// Source row pointer for weight tile; k0 = kt*128 (region-local column)
template <int REGION>
__device__ __forceinline__ const float* wrow(const RnnParams& P, int jg, int k0) {
    if (REGION == 0) {
        if (k0 < 512)  return P.Wrec_m1 + jg * 512 + k0;
        if (k0 < 1024) return P.Wpmd_m1 + jg * 512 + (k0 - 512);
        return P.Ws1_m1 + jg * 512 + (k0 - 1024);
    } else if (REGION == 1) {
        int jp = jg - 512;
        if (k0 < 512) return P.Wm1_pmd + jp * 512 + k0;
        return P.Wrec_pmd + jp * 512 + (k0 - 512);
    } else {
        return P.Wrec_s1 + (jg - 1024) * 512 + k0;
    }
}

// NKW = number of k-windows (16 -> 2 row-halves of 32; 8 -> 4 row-quarters of 16)
template <int NC, int K, int REGION, int NKW>
__device__ __forceinline__ void step_region(const RnnParams& P, int s, int colbase,
                                            int nc, float* sm, int cta)
{
    constexpr int NT  = K / KT;
    constexpr int CT  = NC / 4;              // cols per thread
    constexpr int KWW = 128 / NKW;           // k-window width (floats)
    constexpr int NQ  = KWW / 4;             // quads per window
    constexpr int RT  = (NKW == 16) ? 4 : 2; // rows per thread
    constexpr int RPP = 8 * RT;              // rows per part
    constexpr int KBASE = (REGION == 2) ? 1024 : 0;

    float* Rs[2]; float* Wsb[2];
    Rs[0]  = sm;
    Rs[1]  = sm + 64 * RSP;
    Wsb[0] = sm + 2 * 64 * RSP;
    Wsb[1] = Wsb[0] + NC * WSP;
    float* red = sm;   // overlay (used after mainloop; tiles consumed by then)

    const int tid  = threadIdx.x;
    const int w    = tid >> 5;
    const int lane = tid & 31;
    const int rg   = lane & 7;
    const int cg   = lane >> 3;              // 0..3

    const int kwid = w % NKW;
    const int part = w / NKW;
    const int kw   = kwid * KWW;
    const int rbase = part * RPP;

    const int rb   = s & 1;
    const int wbuf = rb ^ 1;
    const float* Rg = g_R + (size_t)rb * (64 * 1536) + KBASE;

    // ---- stage tile 0 (32 quads per 128-float row) ----
    {
        for (int c = tid; c < 64 * 32; c += 1024) {
            int b = c >> 5, q = c & 31;
            cp16(smaddr(Rs[0] + b * RSP + q * 4), Rg + b * 1536 + q * 4);
        }
        if (tid < NC * 32) {
            int j = tid >> 5, q = tid & 31;
            int jj = (j < nc) ? j : 0;
            cp16(smaddr(Wsb[0] + j * WSP + q * 4),
                 wrow<REGION>(P, colbase + jj, 0) + q * 4);
        }
        cp_commit();
    }

    // ---- previous step's readout (data consistent at launch boundary) ----
    if (s > 0 && w < 5) {
        int p = cta * 5 + w;
        if (p < 640) {
            int b = p / 10, o = p - b * 10;
            const float* Rm = g_R + (size_t)rb * (64 * 1536) + b * 1536;
            const float* Wo = P.Wout + o * 512;
            float sum = 0.f;
            for (int k = lane; k < 512; k += 32) sum += Rm[k] * Wo[k];
#pragma unroll
            for (int off = 16; off; off >>= 1)
                sum += __shfl_down_sync(0xffffffffu, sum, off);
            if (lane == 0) P.out[(size_t)((s - 1) * 64 + b) * 10 + o] = sum;
        }
    }

    // ---- mainloop: packed-k FFMA2, double-buffered tiles ----
    u64t acc2[RT * CT];
#pragma unroll
    for (int i = 0; i < RT * CT; i++) acc2[i] = 0ull;

    for (int kt = 0; kt < NT; kt++) {
        const int buf = kt & 1;
        if (kt + 1 < NT) {
            const int nb = buf ^ 1;
            const int kg = (kt + 1) * KT;
            for (int c = tid; c < 64 * 32; c += 1024) {
                int b = c >> 5, q = c & 31;
                cp16(smaddr(Rs[nb] + b * RSP + q * 4), Rg + b * 1536 + kg + q * 4);
            }
            if (tid < NC * 32) {
                int j = tid >> 5, q = tid & 31;
                int jj = (j < nc) ? j : 0;
                cp16(smaddr(Wsb[nb] + j * WSP + q * 4),
                     wrow<REGION>(P, colbase + jj, kg) + q * 4);
            }
            cp_commit();
            cp_wait<1>();   // tile kt's group done
        } else {
            cp_wait<0>();
        }
        __syncthreads();   // tile kt visible to all warps

        const float* Rt = Rs[buf];
        const float* Wt = Wsb[buf];
#pragma unroll
        for (int q = 0; q < NQ; q++) {
            const int ko = kw + (q << 2);
            ulonglong2 rv[RT];
#pragma unroll
            for (int i = 0; i < RT; i++)
                rv[i] = *(const ulonglong2*)&Rt[(rbase + rg + 8 * i) * RSP + ko];
            ulonglong2 wv[CT];
#pragma unroll
            for (int t = 0; t < CT; t++)
                wv[t] = *(const ulonglong2*)&Wt[(cg + 4 * t) * WSP + ko];
#pragma unroll
            for (int i = 0; i < RT; i++) {
#pragma unroll
                for (int t = 0; t < CT; t++) {
                    FMA_F32X2(acc2[i * CT + t], rv[i].x, wv[t].x);
                    FMA_F32X2(acc2[i * CT + t], rv[i].y, wv[t].y);
                }
            }
        }
        __syncthreads();   // buffer free for restage next iter
    }

    // ---- cross-warp k-partial reduction (overlay smem) ----
#pragma unroll
    for (int t = 0; t < CT; t++) {
        int j = cg + 4 * t;
#pragma unroll
        for (int i = 0; i < RT; i++) {
            int b = rbase + rg + 8 * i;
            float2 p2 = *(float2*)&acc2[i * CT + t];
            red[(kwid * NC + j) * RJ + b] = p2.x + p2.y;
        }
    }
    __syncthreads();

    // ---- epilogue: reduce NKW partials, leaky update + tanh, publish ----
    const float A = 0.1f, OMA = 0.9f;
    const float* bias = (REGION == 0) ? P.b_m1 + colbase
                      : (REGION == 1) ? P.b_pmd + (colbase - 512)
                                      : P.b_s1 + (colbase - 1024);
    float* Rw = g_R + (size_t)wbuf * (64 * 1536);
    const int nout = 64 * nc;
    for (int o = tid; o < nout; o += 1024) {
        int j = o >> 6, b = o & 63;
        float sum = 0.f;
#pragma unroll
        for (int ww = 0; ww < NKW; ww++) sum += red[(ww * NC + j) * RJ + b];
        int jg = colbase + j;
        float v = sum + bias[j];
        if (REGION != 0) v += g_XP[(size_t)(s * 64 + b) * 1024 + (jg - 512)];
        float x = OMA * g_X[jg * 64 + b] + A * v;
        g_X[jg * 64 + b] = x;
        Rw[b * 1536 + jg] = tanhf(x);
    }
}

__global__ void __launch_bounds__(1024, 1) step_kernel(RnnParams P, int s) {
    extern __shared__ float sm[];
    const int cta = blockIdx.x;
    if (cta < 64) {
        step_region<8, 1536, 0, 16>(P, s, cta * 8, 8, sm, cta);
    } else if (cta < 107) {
        int i = cta - 64;
        step_region<12, 1024, 1, 8>(P, s, 512 + i * 12, (i < 42) ? 12 : 8, sm, cta);
    } else {
        int i = cta - 107;
        step_region<16, 512, 2, 8>(P, s, 1024 + i * 16, 16, sm, cta);
    }
}

// --------------------------------------------------------------------------
// Final readout: out[498] from rate buffer 1 (written by step s=498).
// --------------------------------------------------------------------------
__global__ void __launch_bounds__(256) readout_final(const float* __restrict__ Wout,
                                                     float* __restrict__ out)
{
    const int w = threadIdx.x >> 5;
    const int l = threadIdx.x & 31;
    const int p = blockIdx.x * 8 + w;
    if (p >= 640) return;
    int b = p / 10, o = p - b * 10;
    const float* Rm = g_R + (size_t)1 * (64 * 1536) + b * 1536;
    const float* Wo = Wout + o * 512;
    float sum = 0.f;
    for (int k = l; k < 512; k += 32) sum += Rm[k] * Wo[k];
#pragma unroll
    for (int off = 16; off; off >>= 1)
        sum += __shfl_down_sync(0xffffffffu, sum, off);
    if (l == 0) out[(size_t)(498 * 64 + b) * 10 + o] = sum;
}

// ---------------------------------------------------------------------------
static const int XP_SMEM  = (128 * 101 + 100 * 68) * 4;              // 78912 B
static const int RNN_SMEM = (2 * 64 * RSP + 2 * 16 * WSP) * 4;       // 84480 B

extern "C" void kernel_launch(void* const* d_in, const int* in_sizes, int n_in,
                              void* d_out, int out_size)
{
    const float* X        = (const float*)d_in[0];
    const float* Wrec_m1  = (const float*)d_in[1];
    const float* Wrec_pmd = (const float*)d_in[2];
    const float* Wrec_s1  = (const float*)d_in[3];
    const float* b_m1     = (const float*)d_in[4];
    const float* b_pmd    = (const float*)d_in[5];
    const float* b_s1     = (const float*)d_in[6];
    const float* Wpmd_m1  = (const float*)d_in[7];
    const float* Ws1_m1   = (const float*)d_in[8];
    const float* Wm1_pmd  = (const float*)d_in[9];
    const float* W_in_pmd = (const float*)d_in[10];
    const float* W_in_s1  = (const float*)d_in[11];
    const float* Wout     = (const float*)d_in[12];
    float* out = (float*)d_out;

    cudaFuncSetAttribute(xp_kernel,   cudaFuncAttributeMaxDynamicSharedMemorySize, XP_SMEM);
    cudaFuncSetAttribute(step_kernel, cudaFuncAttributeMaxDynamicSharedMemorySize, RNN_SMEM);

    RnnParams P;
    P.Wrec_m1 = Wrec_m1; P.Wrec_pmd = Wrec_pmd; P.Wrec_s1 = Wrec_s1;
    P.b_m1 = b_m1; P.b_pmd = b_pmd; P.b_s1 = b_s1;
    P.Wpmd_m1 = Wpmd_m1; P.Ws1_m1 = Ws1_m1; P.Wm1_pmd = Wm1_pmd;
    P.Wout = Wout; P.out = out;

    init_kernel<<<(64 * 1536 + 255) / 256, 256>>>();
    xp_kernel<<<dim3(8, 499), 256, XP_SMEM>>>(X, W_in_pmd, W_in_s1, b_pmd, b_s1);
    for (int s = 0; s < 499; s++)
        step_kernel<<<NBLK, 1024, RNN_SMEM>>>(P, s);
    readout_final<<<80, 256>>>(Wout, out);
}